// round 13
// baseline (speedup 1.0000x reference)
#include <cuda_runtime.h>

#define BB    16
#define CIN   4
#define DIN   64
#define D1    34
#define D2    19
#define TAPS  343
#define D1SQ  1156
#define D1CU  39304
#define D2SQ  361
#define D2CU  6859
#define D2P   6860
#define NSLOT 36
#define MSLOT 48
#define Y_ELEMS (BB*16*D2CU)    // 1755904
#define M_ELEMS (BB*MSLOT*D2P)  // 5268480 = 20580*256

typedef unsigned long long ull;

// K1 (round-8/11 layout): tile 9x9x12 out, 256 thr (243 live), 4 z/thread, 5 ch-pairs
#define K1_W   1715             // 343 taps * 5 ull (packed channel pairs)
#define K1_IN  15341            // 23*23*29 floats
#define K1_SMEM (K1_W*8 + K1_IN*4)   // 75084 B

// K3: kz-split, tile 10x5x19, x-pair + q-duo, 128 thr (125 live)
#define PLNW  377               // 25*15=375 padded
#define CSTW  (10*PLNW)         // 3770 ull per channel
#define K3W   (49*28)           // 1372 ull weights per kz
#define K3_SMEM ((3*CSTW + K3W)*8)   // 101456 B

// ---------------- scratch ----------------
__device__ float  g_n[(size_t)BB*NSLOT*D1CU];
__device__ float  g_v[(size_t)BB*24*D1CU];
__device__ float  g_m[(size_t)M_ELEMS + 8];
__device__ float  g_y[(size_t)Y_ELEMS];
__device__ ull    g_B1[K1_W];
__device__ ull    g_B2[7*K3W];
__device__ ull    g_W1s[NSLOT*8];
__device__ ull    g_W2s[MSLOT*16];
__device__ double g_sum[16], g_sumsq[16];
__device__ float  g_coef[32];

// ---------------- f32x2 helpers ----------------
__device__ __forceinline__ void ffma2(ull &d, ull a, ull b) {
    asm("fma.rn.f32x2 %0, %1, %2, %0;" : "+l"(d) : "l"(a), "l"(b));
}
__device__ __forceinline__ ull mul2(ull a, ull b) {
    ull r; asm("mul.rn.f32x2 %0, %1, %2;" : "=l"(r) : "l"(a), "l"(b)); return r;
}
__device__ __forceinline__ ull splat2(float v) {
    ull r; unsigned u = __float_as_uint(v);
    asm("mov.b64 %0, {%1, %1};" : "=l"(r) : "r"(u)); return r;
}
__device__ __forceinline__ ull pack2(float lo, float hi) {
    ull r; unsigned a = __float_as_uint(lo), b = __float_as_uint(hi);
    asm("mov.b64 %0, {%1, %2};" : "=l"(r) : "r"(a), "r"(b)); return r;
}
__device__ __forceinline__ float2 unpack2(ull p) {
    unsigned lo, hi;
    asm("mov.b64 {%0, %1}, %2;" : "=r"(lo), "=r"(hi) : "l"(p));
    return make_float2(__uint_as_float(lo), __uint_as_float(hi));
}

// ---------------- setup: zero g_m/stats + all weight tables ------------
__global__ void setup_kernel(const float* __restrict__ basis1,
                             const float* __restrict__ b2a,
                             const float* __restrict__ b2b,
                             const float* __restrict__ W1,
                             const float* __restrict__ W2a,
                             const float* __restrict__ W2b) {
    int idx = blockIdx.x * 256 + threadIdx.x;   // grid exactly M_ELEMS/256
    g_m[idx] = 0.f;
    if (idx < 16) { g_sum[idx] = 0.0; g_sumsq[idx] = 0.0; }
    if (idx >= M_ELEMS - 8 && idx < M_ELEMS) g_m[idx + 8] = 0.f;

    // B1: pair-packed basis1, [tap*5+p] = (ch 2p, ch 2p+1), ch = b*3+i
    if (idx < K1_W) {
        int tap = idx / 5, p = idx % 5;
        float w0 = basis1[(2*p)*TAPS + tap];
        float w1 = (2*p + 1 < 9) ? basis1[(2*p+1)*TAPS + tap] : 0.f;
        g_B1[idx] = pack2(w0, w1);
    }
    // B2: [kz][kyx][e] splatted, 28 ull per tap (27 used)
    int j = idx - K1_W;
    if (j >= 0 && j < 7*K3W) {
        int kz = j / K3W;
        int r  = j % K3W;
        int kyx = r / 28, e = r % 28;
        int tap = kz*49 + kyx;
        float w = 0.f;
        if (e < 9) {
            int b3 = e / 3, i = e % 3;
            w = b2a[(b3*3 + i)*TAPS + tap];
        } else if (e < 27) {
            const int IA[6] = {0,0,0,1,1,2};
            const int JA[6] = {0,1,2,1,2,2};
            int e2 = e - 9;
            int b3 = e2 / 6, ic = e2 % 6;
            int ii = IA[ic], jj = JA[ic];
            w = b2b[(b3*9 + ii*3 + jj)*TAPS + tap];
            if (ii != jj) w += b2b[(b3*9 + jj*3 + ii)*TAPS + tap];
        }
        g_B2[j] = pack2(w, w);
    }
    // W1s: [slot*8+u] = splat(W1[u][ci][b3]) ; slot = ci*9 + c, c = b3*3+i
    int k = idx - K1_W - 7*K3W;
    if (k >= 0 && k < NSLOT*8) {
        int sl = k / 8, u = k % 8;
        int ci = sl / 9, c = sl % 9, b3 = c / 3;
        g_W1s[k] = splat2(W1[(u*CIN + ci)*3 + b3]);
    }
    // W2s: [s*16+co] ; s = u*6 + jj (jj<3: a, else b)
    int l = idx - K1_W - 7*K3W - NSLOT*8;
    if (l >= 0 && l < MSLOT*16) {
        int s = l / 16, co = l % 16;
        int u = s / 6, jj = s % 6;
        float w = (jj < 3) ? W2a[(co*8 + u)*3 + jj]
                           : W2b[(co*8 + u)*3 + (jj-3)];
        g_W2s[l] = splat2(w);
    }
}

// ---------------- K1 (round-11): basis conv1, s -> n[16,36,34^3] ----------
__global__ __launch_bounds__(256, 2)
void k1_kernel(const float* __restrict__ s) {
    extern __shared__ char smraw[];
    ull*   smw = (ull*)smraw;                 // K1_W
    float* smi = (float*)(smraw + K1_W*8);    // K1_IN

    int tid = threadIdx.x;
    int b  = blockIdx.z / 3;
    int zt = blockIdx.z % 3;
    int ox0 = blockIdx.x * 9, oy0 = blockIdx.y * 9, oz0 = zt * 12;
    int ix0 = 2*ox0 - 5, iy0 = 2*oy0 - 5, iz0 = 2*oz0 - 5;

    int lx = tid % 9;
    int rr = tid / 9;
    int ly = rr % 9;
    int lz3 = rr / 9;
    bool live = (lz3 < 3);
    int lz = live ? lz3 : 0;

    for (int t = tid; t < K1_W; t += 256) smw[t] = g_B1[t];

    for (int ci = 0; ci < CIN; ci++) {
        __syncthreads();
        {
            const float* sp = s + ((size_t)b*CIN + ci) * (DIN*DIN*DIN);
            for (int t = tid; t < K1_IN; t += 256) {
                int dx = t % 23;
                int r  = t / 23;
                int dy = r % 23;
                int dz = r / 23;
                int ix = ix0 + dx, iy = iy0 + dy, iz = iz0 + dz;
                float v = 0.f;
                if ((unsigned)ix < DIN && (unsigned)iy < DIN && (unsigned)iz < DIN)
                    v = sp[((size_t)iz*DIN + iy)*DIN + ix];
                smi[t] = v;
            }
        }
        __syncthreads();

        ull acc[20];
#pragma unroll
        for (int q = 0; q < 20; q++) acc[q] = 0ULL;

#pragma unroll 1
        for (int kz = 0; kz < 7; kz++) {
#pragma unroll 1
            for (int ky = 0; ky < 7; ky++) {
                const float* r0 = &smi[(2*lz + kz)*529 + (2*ly + ky)*23 + 2*lx];
                const ull* wrow = &smw[(kz*7 + ky)*35];
#pragma unroll
                for (int kx = 0; kx < 7; kx++) {
                    ull w0 = wrow[kx*5+0], w1 = wrow[kx*5+1], w2 = wrow[kx*5+2];
                    ull w3 = wrow[kx*5+3], w4 = wrow[kx*5+4];
#pragma unroll
                    for (int k = 0; k < 4; k++) {
                        ull a = splat2(r0[kx + k*3174]);   // z plane +6k
                        ffma2(acc[k],    a, w0);
                        ffma2(acc[4+k],  a, w1);
                        ffma2(acc[8+k],  a, w2);
                        ffma2(acc[12+k], a, w3);
                        ffma2(acc[16+k], a, w4);
                    }
                }
            }
        }

        int ox = ox0 + lx, oy = oy0 + ly;
        if (live && ox < D1 && oy < D1) {
#pragma unroll
            for (int k = 0; k < 4; k++) {
                int oz = oz0 + lz + 3*k;
                if (oz < D1) {
                    size_t base = ((size_t)b*NSLOT + ci*9)*D1CU
                                + (size_t)oz*D1SQ + oy*D1 + ox;
#pragma unroll
                    for (int p = 0; p < 5; p++) {
                        float2 f = unpack2(acc[p*4 + k]);
                        g_n[base + (size_t)(2*p)*D1CU] = f.x;
                        if (p < 4) g_n[base + (size_t)(2*p+1)*D1CU] = f.y;
                    }
                }
            }
        }
    }
}

// ---------------- C1: combine n -> v[16,24,34^3] ----------------
__global__ void c1_kernel() {
    __shared__ ull tw[NSLOT*8];
    int tid = threadIdx.x;
    for (int t = tid; t < NSLOT*8; t += 256) tw[t] = g_W1s[t];
    __syncthreads();
    size_t idx = (size_t)blockIdx.x * 256 + tid;
    if (idx >= (size_t)BB * (D1CU/2)) return;
    int b  = (int)(idx / (D1CU/2));
    int t2 = (int)(idx % (D1CU/2));

    const float2* np = (const float2*)(g_n + (size_t)b*NSLOT*D1CU) + t2;
    ull acc[24];
#pragma unroll
    for (int c = 0; c < 24; c++) acc[c] = 0ULL;
#pragma unroll
    for (int sl = 0; sl < NSLOT; sl++) {
        float2 f = np[(size_t)sl * (D1CU/2)];
        ull m = pack2(f.x, f.y);
        int i = (sl % 9) % 3;
#pragma unroll
        for (int u = 0; u < 8; u++)
            ffma2(acc[u*3 + i], m, tw[sl*8 + u]);
    }
    float2* vp = (float2*)(g_v + (size_t)b*24*D1CU) + t2;
#pragma unroll
    for (int c = 0; c < 24; c++) {
        float2 f = unpack2(acc[c]);
        vp[(size_t)c * (D1CU/2)] = f;
    }
}

// ---------------- K3: basis conv2, kz-split, x-pair + q-duo ----------
// tile 10x5x19; 128 thr (125 live); thread (lx,ly,qd) computes
// positions (ox0+lx, ox0+lx+5) for q-slots qd and qd+5 (each slot = z lanes q,q+10)
__global__ __launch_bounds__(128, 2)
void k3_kernel() {
    extern __shared__ ull smu[];
    ull* sv  = smu;              // 3 * CSTW
    ull* smw = smu + 3*CSTW;     // K3W

    int tid = threadIdx.x;
    int kz = blockIdx.z % 7;
    int b  = blockIdx.z / 7;
    int ox0 = blockIdx.x * 10, oy0 = blockIdx.y * 5;

    int lx = tid % 5;
    int rr = tid / 5;
    int ly = rr % 5;
    int qd5 = rr / 5;            // 0..5 (125..127 -> 5)
    bool live = (qd5 < 5);
    int qd = live ? qd5 : 0;

    for (int t = tid; t < K3W; t += 128) smw[t] = g_B2[kz*K3W + t];

    for (int u = 0; u < 8; u++) {
        __syncthreads();
        for (int c = 0; c < 3; c++) {
            const float* vp = g_v + ((size_t)b*24 + u*3 + c) * D1CU;
            for (int t = tid; t < 10*375; t += 128) {
                int xl = t % 25;
                int r2 = t / 25;
                int yl = r2 % 15;
                int p  = r2 / 15;
                int ix = 2*ox0 - 5 + xl;
                int iy = 2*oy0 - 5 + yl;
                int izA = 2*p + kz - 5;
                int izB = izA + 20;
                float a = 0.f, bb = 0.f;
                bool xy = ((unsigned)ix < D1 && (unsigned)iy < D1);
                if (xy && (unsigned)izA < D1) a  = vp[(size_t)izA*D1SQ + iy*D1 + ix];
                if (xy && (unsigned)izB < D1) bb = vp[(size_t)izB*D1SQ + iy*D1 + ix];
                sv[c*CSTW + p*PLNW + yl*25 + xl] = pack2(a, bb);
            }
        }
        __syncthreads();

        ull acc[24];   // [qs 0..1][pos 0..1][j 0..5]
#pragma unroll
        for (int j = 0; j < 24; j++) acc[j] = 0ULL;

        const ull* p0 = &sv[qd*PLNW + (2*ly)*25 + 2*lx];
        const ull* p1 = p0 + 5*PLNW;     // q-slot qd+5
#pragma unroll 1
        for (int ky = 0; ky < 7; ky++) {
#pragma unroll 1
            for (int kx = 0; kx < 7; kx++) {
                int off = ky*25 + kx;
                const ull* w = &smw[(ky*7 + kx)*28];
#pragma unroll
                for (int qs = 0; qs < 2; qs++) {
                    const ull* pi = (qs == 0) ? (p0 + off) : (p1 + off);
                    ull* ac = acc + qs*12;
                    ull va0 = pi[0],  va1 = pi[CSTW],    va2 = pi[2*CSTW];
                    ull vb0 = pi[10], vb1 = pi[10+CSTW], vb2 = pi[10+2*CSTW];
                    // a-parts (vector channels), both positions share weights
                    ffma2(ac[0], va0, w[0]); ffma2(ac[1], va0, w[3]); ffma2(ac[2], va0, w[6]);
                    ffma2(ac[6], vb0, w[0]); ffma2(ac[7], vb0, w[3]); ffma2(ac[8], vb0, w[6]);
                    ffma2(ac[0], va1, w[1]); ffma2(ac[1], va1, w[4]); ffma2(ac[2], va1, w[7]);
                    ffma2(ac[6], vb1, w[1]); ffma2(ac[7], vb1, w[4]); ffma2(ac[8], vb1, w[7]);
                    ffma2(ac[0], va2, w[2]); ffma2(ac[1], va2, w[5]); ffma2(ac[2], va2, w[8]);
                    ffma2(ac[6], vb2, w[2]); ffma2(ac[7], vb2, w[5]); ffma2(ac[8], vb2, w[8]);
                    // symmetric products, both positions
                    ull pa[6], pb[6];
                    pa[0] = mul2(va0, va0); pb[0] = mul2(vb0, vb0);
                    pa[1] = mul2(va0, va1); pb[1] = mul2(vb0, vb1);
                    pa[2] = mul2(va0, va2); pb[2] = mul2(vb0, vb2);
                    pa[3] = mul2(va1, va1); pb[3] = mul2(vb1, vb1);
                    pa[4] = mul2(va1, va2); pb[4] = mul2(vb1, vb2);
                    pa[5] = mul2(va2, va2); pb[5] = mul2(vb2, vb2);
#pragma unroll
                    for (int ic = 0; ic < 6; ic++) {
                        ull w3 = w[9 + ic], w4 = w[15 + ic], w5 = w[21 + ic];
                        ffma2(ac[3],  pa[ic], w3);
                        ffma2(ac[4],  pa[ic], w4);
                        ffma2(ac[5],  pa[ic], w5);
                        ffma2(ac[9],  pb[ic], w3);
                        ffma2(ac[10], pb[ic], w4);
                        ffma2(ac[11], pb[ic], w5);
                    }
                }
            }
        }

        int oy = oy0 + ly;
        if (live && oy < D2) {
#pragma unroll
            for (int qs = 0; qs < 2; qs++) {
                int qq = qd + 5*qs;
#pragma unroll
                for (int pos = 0; pos < 2; pos++) {
                    int ox = ox0 + lx + 5*pos;
                    if (ox < D2) {
#pragma unroll
                        for (int j = 0; j < 6; j++) {
                            float2 f = unpack2(acc[qs*12 + pos*6 + j]);
                            size_t base = ((size_t)b*MSLOT + u*6 + j)*D2P + oy*D2 + ox;
                            atomicAdd(&g_m[base + (size_t)qq*D2SQ], f.x);
                            if (qq < 9) atomicAdd(&g_m[base + (size_t)(qq+10)*D2SQ], f.y);
                        }
                    }
                }
            }
        }
    }
}

// ---------------- C2: combine m -> y + fused BN stats ----------------
__global__ void c2_kernel() {
    __shared__ ull tw[MSLOT*16];
    __shared__ float red[2*8*16];
    int tid = threadIdx.x;
    for (int t = tid; t < MSLOT*16; t += 256) tw[t] = g_W2s[t];
    __syncthreads();

    int idx = blockIdx.x * 256 + tid;
    bool vt = (idx < BB*3430);
    int b  = vt ? idx / 3430 : 0;
    int t2 = vt ? idx % 3430 : 0;
    bool hasHi = vt && (2*t2 + 1 < D2CU);

    const float* mb = g_m + (size_t)b*MSLOT*D2P + 2*t2;
    ull acc[16];
#pragma unroll
    for (int c = 0; c < 16; c++) acc[c] = 0ULL;
#pragma unroll 4
    for (int s = 0; s < MSLOT; s++) {
        float2 f = *(const float2*)(mb + (size_t)s*D2P);
        ull m = pack2(f.x, f.y);
#pragma unroll
        for (int co = 0; co < 16; co++)
            ffma2(acc[co], m, tw[s*16 + co]);
    }

    float ylo[16], yhi[16];
#pragma unroll
    for (int co = 0; co < 16; co++) {
        float2 f = unpack2(acc[co]);
        ylo[co] = f.x; yhi[co] = f.y;
        if (vt) {
            size_t base = ((size_t)b*16 + co)*D2CU + 2*t2;
            g_y[base] = f.x;
            if (hasHi) g_y[base + 1] = f.y;
        }
    }

    int lane = tid & 31, wid = tid >> 5;
#pragma unroll
    for (int co = 0; co < 16; co++) {
        float s1 = 0.f, s2 = 0.f;
        if (vt)    { s1 += ylo[co]; s2 += ylo[co]*ylo[co]; }
        if (hasHi) { s1 += yhi[co]; s2 += yhi[co]*yhi[co]; }
#pragma unroll
        for (int o = 16; o > 0; o >>= 1) {
            s1 += __shfl_down_sync(0xffffffffu, s1, o);
            s2 += __shfl_down_sync(0xffffffffu, s2, o);
        }
        if (lane == 0) {
            red[wid*16 + co]       = s1;
            red[128 + wid*16 + co] = s2;
        }
    }
    __syncthreads();
    if (tid < 16) {
        float s1 = 0.f, s2 = 0.f;
#pragma unroll
        for (int w = 0; w < 8; w++) {
            s1 += red[w*16 + tid];
            s2 += red[128 + w*16 + tid];
        }
        atomicAdd(&g_sum[tid],   (double)s1);
        atomicAdd(&g_sumsq[tid], (double)s2);
    }
}

// ---------------- BN coefficients ----------------
__global__ void coef_kernel(const float* __restrict__ gamma,
                            const float* __restrict__ beta,
                            const float* __restrict__ bias) {
    int c = threadIdx.x;
    if (c < 16) {
        double N = (double)BB * (double)D2CU;
        double mean = g_sum[c] / N;
        double var  = g_sumsq[c] / N - mean*mean;
        float a = gamma[c] * rsqrtf((float)var + 1e-5f);
        g_coef[c]      = a;
        g_coef[16 + c] = beta[c] - a * (float)mean + bias[c];
    }
}

// ---------------- BN apply + bias + relu ----------------
__global__ void apply_kernel(float* __restrict__ out) {
    int idx = blockIdx.x * 256 + threadIdx.x;   // exactly Y_ELEMS
    int c = (idx / D2CU) & 15;
    float a = g_coef[c], b = g_coef[16 + c];
    out[idx] = fmaxf(fmaf(a, g_y[idx], b), 0.f);
}

// ---------------- launch ----------------
extern "C" void kernel_launch(void* const* d_in, const int* in_sizes, int n_in,
                              void* d_out, int out_size) {
    (void)in_sizes; (void)n_in; (void)out_size;
    const float* s       = (const float*)d_in[0];
    const float* basis1  = (const float*)d_in[1];
    const float* W1      = (const float*)d_in[2];
    const float* basis2a = (const float*)d_in[3];
    const float* basis2b = (const float*)d_in[4];
    const float* W2a     = (const float*)d_in[5];
    const float* W2b     = (const float*)d_in[6];
    const float* gamma   = (const float*)d_in[7];
    const float* beta    = (const float*)d_in[8];
    const float* bias    = (const float*)d_in[9];
    float* out = (float*)d_out;

    cudaFuncSetAttribute(k1_kernel,
        cudaFuncAttributeMaxDynamicSharedMemorySize, K1_SMEM);
    cudaFuncSetAttribute(k3_kernel,
        cudaFuncAttributeMaxDynamicSharedMemorySize, K3_SMEM);

    // launch order keeps k3 in the profiler's captured (4th) slot
    setup_kernel<<<M_ELEMS/256, 256>>>(basis1, basis2a, basis2b, W1, W2a, W2b);
    k1_kernel<<<dim3(4, 4, BB*3), 256, K1_SMEM>>>(s);
    c1_kernel<<<(BB*(D1CU/2) + 255)/256, 256>>>();
    k3_kernel<<<dim3(2, 4, BB*7), 128, K3_SMEM>>>();
    c2_kernel<<<(BB*3430 + 255)/256, 256>>>();
    coef_kernel<<<1, 16>>>(gamma, beta, bias);
    apply_kernel<<<Y_ELEMS/256, 256>>>(out);
}

// round 15
// speedup vs baseline: 1.0783x; 1.0783x over previous
#include <cuda_runtime.h>

#define BB    16
#define CIN   4
#define DIN   64
#define D1    34
#define D2    19
#define TAPS  343
#define D1SQ  1156
#define D1CU  39304
#define D2SQ  361
#define D2CU  6859
#define NSLOT 36
#define MSLOT 48
#define Y_ELEMS (BB*16*D2CU)    // 1755904

typedef unsigned long long ull;

// K1 (round-11 best): tile 9x9x12 out, 256 thr (243 live), 4 z/thread, 5 ch-pairs
#define K1_W   1715             // 343 taps * 5 ull (packed channel pairs)
#define K1_IN  15341            // 23*23*29 floats
#define K1_SMEM (K1_W*8 + K1_IN*4)   // 75084 B

// K3: kz-split, tile 10x5x19, x-pair, PARITY input layout, 256 thr (250 live)
// halo row: 13 even-x + 12 odd-x + 1 pad = 26 ull
#define ROW2  26
#define PST2  391               // 15*26 + 1 pad (plane stride, ull)
#define CST2  3910              // 10 planes per channel
#define K3W   (49*28)           // 1372 ull weights per kz
#define K3_SMEM ((3*CST2 + K3W)*8)   // 104816 B  (2 blocks/SM = 204.7 KB)

// m with kz dimension: [kz][b][s][q(0..9)][19*19], packed z-pairs (q, q+10)
#define MQ    3610              // 10*361
#define KZSTR ((size_t)BB*MSLOT*MQ)  // 2772480
#define M7_ELEMS ((size_t)7*KZSTR)   // 19,407,360 ull = 155.3 MB

// ---------------- scratch ----------------
__device__ float  g_n[(size_t)BB*NSLOT*D1CU];
__device__ float  g_v[(size_t)BB*24*D1CU];
__device__ ull    g_m7[M7_ELEMS];
__device__ float  g_y[(size_t)Y_ELEMS];
__device__ ull    g_B1[K1_W];
__device__ ull    g_B2[7*K3W];
__device__ ull    g_W1s[NSLOT*8];
__device__ ull    g_W2s[MSLOT*16];
__device__ double g_sum[16], g_sumsq[16];
__device__ float  g_coef[32];

// ---------------- f32x2 helpers ----------------
__device__ __forceinline__ void ffma2(ull &d, ull a, ull b) {
    asm("fma.rn.f32x2 %0, %1, %2, %0;" : "+l"(d) : "l"(a), "l"(b));
}
__device__ __forceinline__ ull mul2(ull a, ull b) {
    ull r; asm("mul.rn.f32x2 %0, %1, %2;" : "=l"(r) : "l"(a), "l"(b)); return r;
}
__device__ __forceinline__ void add2(ull &d, ull a) {
    asm("add.rn.f32x2 %0, %0, %1;" : "+l"(d) : "l"(a));
}
__device__ __forceinline__ ull splat2(float v) {
    ull r; unsigned u = __float_as_uint(v);
    asm("mov.b64 %0, {%1, %1};" : "=l"(r) : "r"(u)); return r;
}
__device__ __forceinline__ ull pack2(float lo, float hi) {
    ull r; unsigned a = __float_as_uint(lo), b = __float_as_uint(hi);
    asm("mov.b64 %0, {%1, %2};" : "=l"(r) : "r"(a), "r"(b)); return r;
}
__device__ __forceinline__ float2 unpack2(ull p) {
    unsigned lo, hi;
    asm("mov.b64 {%0, %1}, %2;" : "=r"(lo), "=r"(hi) : "l"(p));
    return make_float2(__uint_as_float(lo), __uint_as_float(hi));
}

// ---------------- setup: stats + weight tables (no g_m zeroing needed) ----
__global__ void setup_kernel(const float* __restrict__ basis1,
                             const float* __restrict__ b2a,
                             const float* __restrict__ b2b,
                             const float* __restrict__ W1,
                             const float* __restrict__ W2a,
                             const float* __restrict__ W2b) {
    int idx = blockIdx.x * 256 + threadIdx.x;
    if (idx < 16) { g_sum[idx] = 0.0; g_sumsq[idx] = 0.0; }

    if (idx < K1_W) {
        int tap = idx / 5, p = idx % 5;
        float w0 = basis1[(2*p)*TAPS + tap];
        float w1 = (2*p + 1 < 9) ? basis1[(2*p+1)*TAPS + tap] : 0.f;
        g_B1[idx] = pack2(w0, w1);
    }
    int j = idx - K1_W;
    if (j >= 0 && j < 7*K3W) {
        int kz = j / K3W;
        int r  = j % K3W;
        int kyx = r / 28, e = r % 28;
        int tap = kz*49 + kyx;
        float w = 0.f;
        if (e < 9) {
            int b3 = e / 3, i = e % 3;
            w = b2a[(b3*3 + i)*TAPS + tap];
        } else if (e < 27) {
            const int IA[6] = {0,0,0,1,1,2};
            const int JA[6] = {0,1,2,1,2,2};
            int e2 = e - 9;
            int b3 = e2 / 6, ic = e2 % 6;
            int ii = IA[ic], jj = JA[ic];
            w = b2b[(b3*9 + ii*3 + jj)*TAPS + tap];
            if (ii != jj) w += b2b[(b3*9 + jj*3 + ii)*TAPS + tap];
        }
        g_B2[j] = pack2(w, w);
    }
    int k = idx - K1_W - 7*K3W;
    if (k >= 0 && k < NSLOT*8) {
        int sl = k / 8, u = k % 8;
        int ci = sl / 9, c = sl % 9, b3 = c / 3;
        g_W1s[k] = splat2(W1[(u*CIN + ci)*3 + b3]);
    }
    int l = idx - K1_W - 7*K3W - NSLOT*8;
    if (l >= 0 && l < MSLOT*16) {
        int s = l / 16, co = l % 16;
        int u = s / 6, jj = s % 6;
        float w = (jj < 3) ? W2a[(co*8 + u)*3 + jj]
                           : W2b[(co*8 + u)*3 + (jj-3)];
        g_W2s[l] = splat2(w);
    }
}

// ---------------- K1 (round-11): basis conv1, s -> n[16,36,34^3] ----------
__global__ __launch_bounds__(256, 2)
void k1_kernel(const float* __restrict__ s) {
    extern __shared__ char smraw[];
    ull*   smw = (ull*)smraw;                 // K1_W
    float* smi = (float*)(smraw + K1_W*8);    // K1_IN

    int tid = threadIdx.x;
    int b  = blockIdx.z / 3;
    int zt = blockIdx.z % 3;
    int ox0 = blockIdx.x * 9, oy0 = blockIdx.y * 9, oz0 = zt * 12;
    int ix0 = 2*ox0 - 5, iy0 = 2*oy0 - 5, iz0 = 2*oz0 - 5;

    int lx = tid % 9;
    int rr = tid / 9;
    int ly = rr % 9;
    int lz3 = rr / 9;
    bool live = (lz3 < 3);
    int lz = live ? lz3 : 0;

    for (int t = tid; t < K1_W; t += 256) smw[t] = g_B1[t];

    for (int ci = 0; ci < CIN; ci++) {
        __syncthreads();
        {
            const float* sp = s + ((size_t)b*CIN + ci) * (DIN*DIN*DIN);
            for (int t = tid; t < K1_IN; t += 256) {
                int dx = t % 23;
                int r  = t / 23;
                int dy = r % 23;
                int dz = r / 23;
                int ix = ix0 + dx, iy = iy0 + dy, iz = iz0 + dz;
                float v = 0.f;
                if ((unsigned)ix < DIN && (unsigned)iy < DIN && (unsigned)iz < DIN)
                    v = sp[((size_t)iz*DIN + iy)*DIN + ix];
                smi[t] = v;
            }
        }
        __syncthreads();

        ull acc[20];
#pragma unroll
        for (int q = 0; q < 20; q++) acc[q] = 0ULL;

#pragma unroll 1
        for (int kz = 0; kz < 7; kz++) {
#pragma unroll 1
            for (int ky = 0; ky < 7; ky++) {
                const float* r0 = &smi[(2*lz + kz)*529 + (2*ly + ky)*23 + 2*lx];
                const ull* wrow = &smw[(kz*7 + ky)*35];
#pragma unroll
                for (int kx = 0; kx < 7; kx++) {
                    ull w0 = wrow[kx*5+0], w1 = wrow[kx*5+1], w2 = wrow[kx*5+2];
                    ull w3 = wrow[kx*5+3], w4 = wrow[kx*5+4];
#pragma unroll
                    for (int k = 0; k < 4; k++) {
                        ull a = splat2(r0[kx + k*3174]);   // z plane +6k
                        ffma2(acc[k],    a, w0);
                        ffma2(acc[4+k],  a, w1);
                        ffma2(acc[8+k],  a, w2);
                        ffma2(acc[12+k], a, w3);
                        ffma2(acc[16+k], a, w4);
                    }
                }
            }
        }

        int ox = ox0 + lx, oy = oy0 + ly;
        if (live && ox < D1 && oy < D1) {
#pragma unroll
            for (int k = 0; k < 4; k++) {
                int oz = oz0 + lz + 3*k;
                if (oz < D1) {
                    size_t base = ((size_t)b*NSLOT + ci*9)*D1CU
                                + (size_t)oz*D1SQ + oy*D1 + ox;
#pragma unroll
                    for (int p = 0; p < 5; p++) {
                        float2 f = unpack2(acc[p*4 + k]);
                        g_n[base + (size_t)(2*p)*D1CU] = f.x;
                        if (p < 4) g_n[base + (size_t)(2*p+1)*D1CU] = f.y;
                    }
                }
            }
        }
    }
}

// ---------------- C1: combine n -> v[16,24,34^3] ----------------
__global__ void c1_kernel() {
    __shared__ ull tw[NSLOT*8];
    int tid = threadIdx.x;
    for (int t = tid; t < NSLOT*8; t += 256) tw[t] = g_W1s[t];
    __syncthreads();
    size_t idx = (size_t)blockIdx.x * 256 + tid;
    if (idx >= (size_t)BB * (D1CU/2)) return;
    int b  = (int)(idx / (D1CU/2));
    int t2 = (int)(idx % (D1CU/2));

    const float2* np = (const float2*)(g_n + (size_t)b*NSLOT*D1CU) + t2;
    ull acc[24];
#pragma unroll
    for (int c = 0; c < 24; c++) acc[c] = 0ULL;
#pragma unroll
    for (int sl = 0; sl < NSLOT; sl++) {
        float2 f = np[(size_t)sl * (D1CU/2)];
        ull m = pack2(f.x, f.y);
        int i = (sl % 9) % 3;
#pragma unroll
        for (int u = 0; u < 8; u++)
            ffma2(acc[u*3 + i], m, tw[sl*8 + u]);
    }
    float2* vp = (float2*)(g_v + (size_t)b*24*D1CU) + t2;
#pragma unroll
    for (int c = 0; c < 24; c++) {
        float2 f = unpack2(acc[c]);
        vp[(size_t)c * (D1CU/2)] = f;
    }
}

// ---------------- K3: basis conv2, kz-split, x-pair, parity layout --------
// tile 10x5x19; thread (lx,ly,q): positions (ox0+lx, ox0+lx+5), z pair (q,q+10).
// Input rows split even/odd x -> stride-1 conflict-free LDS.
// Outputs: plain packed STG.64 into per-kz m slices (no atomics).
__global__ __launch_bounds__(256, 2)
void k3_kernel() {
    extern __shared__ ull smu[];
    ull* sv  = smu;              // 3 * CST2
    ull* smw = smu + 3*CST2;     // K3W

    int tid = threadIdx.x;
    int kz = blockIdx.z % 7;
    int b  = blockIdx.z / 7;
    int ox0 = blockIdx.x * 10, oy0 = blockIdx.y * 5;

    int lx = tid % 5;
    int rr = tid / 5;
    int ly = rr % 5;
    int q10 = rr / 5;
    bool live = (q10 < 10);
    int q = live ? q10 : 0;

    for (int t = tid; t < K3W; t += 256) smw[t] = g_B2[kz*K3W + t];

    for (int u = 0; u < 8; u++) {
        __syncthreads();
        for (int c = 0; c < 3; c++) {
            const float* vp = g_v + ((size_t)b*24 + u*3 + c) * D1CU;
            for (int t = tid; t < 10*390; t += 256) {
                int ent = t % ROW2;
                int r2  = t / ROW2;
                int yl  = r2 % 15;
                int p   = r2 / 15;
                if (ent < 25) {
                    int xh = (ent < 13) ? 2*ent : 2*(ent - 13) + 1;
                    int ix = 2*ox0 - 5 + xh;
                    int iy = 2*oy0 - 5 + yl;
                    int izA = 2*p + kz - 5;
                    int izB = izA + 20;
                    float a = 0.f, bb = 0.f;
                    bool xy = ((unsigned)ix < D1 && (unsigned)iy < D1);
                    if (xy && (unsigned)izA < D1) a  = vp[(size_t)izA*D1SQ + iy*D1 + ix];
                    if (xy && (unsigned)izB < D1) bb = vp[(size_t)izB*D1SQ + iy*D1 + ix];
                    sv[c*CST2 + p*PST2 + yl*ROW2 + ent] = pack2(a, bb);
                }
            }
        }
        __syncthreads();

        ull acc[12];   // [pos 0..1][j 0..5]
#pragma unroll
        for (int j = 0; j < 12; j++) acc[j] = 0ULL;

        const ull* pb = &sv[q*PST2 + (2*ly)*ROW2 + lx];
#pragma unroll 1
        for (int ky = 0; ky < 7; ky++) {
            const ull* pr = pb + ky*ROW2;
            const ull* wr = &smw[ky*7*28];
#pragma unroll
            for (int kx = 0; kx < 7; kx++) {
                const int KXO[7] = {0, 13, 1, 14, 2, 15, 3};
                const ull* pi = pr + KXO[kx];
                const ull* w  = wr + kx*28;
                ull va0 = pi[0], va1 = pi[CST2],   va2 = pi[2*CST2];
                ull vb0 = pi[5], vb1 = pi[5+CST2], vb2 = pi[5+2*CST2];
                // a-parts (vector channels), both positions share weights
                ffma2(acc[0], va0, w[0]); ffma2(acc[1], va0, w[3]); ffma2(acc[2], va0, w[6]);
                ffma2(acc[6], vb0, w[0]); ffma2(acc[7], vb0, w[3]); ffma2(acc[8], vb0, w[6]);
                ffma2(acc[0], va1, w[1]); ffma2(acc[1], va1, w[4]); ffma2(acc[2], va1, w[7]);
                ffma2(acc[6], vb1, w[1]); ffma2(acc[7], vb1, w[4]); ffma2(acc[8], vb1, w[7]);
                ffma2(acc[0], va2, w[2]); ffma2(acc[1], va2, w[5]); ffma2(acc[2], va2, w[8]);
                ffma2(acc[6], vb2, w[2]); ffma2(acc[7], vb2, w[5]); ffma2(acc[8], vb2, w[8]);
                // symmetric products, both positions
                ull pa[6], pbv[6];
                pa[0] = mul2(va0, va0); pbv[0] = mul2(vb0, vb0);
                pa[1] = mul2(va0, va1); pbv[1] = mul2(vb0, vb1);
                pa[2] = mul2(va0, va2); pbv[2] = mul2(vb0, vb2);
                pa[3] = mul2(va1, va1); pbv[3] = mul2(vb1, vb1);
                pa[4] = mul2(va1, va2); pbv[4] = mul2(vb1, vb2);
                pa[5] = mul2(va2, va2); pbv[5] = mul2(vb2, vb2);
#pragma unroll
                for (int ic = 0; ic < 6; ic++) {
                    ull w3 = w[9 + ic], w4 = w[15 + ic], w5 = w[21 + ic];
                    ffma2(acc[3],  pa[ic],  w3);
                    ffma2(acc[4],  pa[ic],  w4);
                    ffma2(acc[5],  pa[ic],  w5);
                    ffma2(acc[9],  pbv[ic], w3);
                    ffma2(acc[10], pbv[ic], w4);
                    ffma2(acc[11], pbv[ic], w5);
                }
            }
        }

        int oy = oy0 + ly;
        if (live && oy < D2) {
            size_t mb = ((size_t)(kz*BB + b)*MSLOT + u*6)*MQ
                      + (size_t)q*D2SQ + oy*D2;
#pragma unroll
            for (int pos = 0; pos < 2; pos++) {
                int ox = ox0 + lx + 5*pos;
                if (ox < D2) {
#pragma unroll
                    for (int j = 0; j < 6; j++)
                        g_m7[mb + (size_t)j*MQ + ox] = acc[pos*6 + j];
                }
            }
        }
    }
}

// ---------------- C2: sum kz slices + combine m -> y + BN stats ----------
__global__ void c2_kernel() {
    __shared__ ull tw[MSLOT*16];
    __shared__ float red[2*8*16];
    int tid = threadIdx.x;
    for (int t = tid; t < MSLOT*16; t += 256) tw[t] = g_W2s[t];
    __syncthreads();

    int idx = blockIdx.x * 256 + tid;        // over BB*MQ = 57760
    bool vt = (idx < BB*MQ);
    int b = vt ? idx / MQ : 0;
    int r = vt ? idx % MQ : 0;
    int q  = r / D2SQ;
    int sp = r % D2SQ;
    bool hasHi = vt && (q < 9);

    const ull* mb = g_m7 + (size_t)b*MSLOT*MQ + r;
    ull acc[16];
#pragma unroll
    for (int c = 0; c < 16; c++) acc[c] = 0ULL;
#pragma unroll 4
    for (int s = 0; s < MSLOT; s++) {
        const ull* ms = mb + (size_t)s*MQ;
        ull v = ms[0];
#pragma unroll
        for (int kzi = 1; kzi < 7; kzi++) add2(v, ms[(size_t)kzi*KZSTR]);
#pragma unroll
        for (int co = 0; co < 16; co++)
            ffma2(acc[co], v, tw[s*16 + co]);
    }

    float ylo[16], yhi[16];
#pragma unroll
    for (int co = 0; co < 16; co++) {
        float2 f = unpack2(acc[co]);
        ylo[co] = f.x; yhi[co] = f.y;
        if (vt) {
            size_t base = ((size_t)b*16 + co)*D2CU + sp;
            g_y[base + (size_t)q*D2SQ] = f.x;
            if (hasHi) g_y[base + (size_t)(q+10)*D2SQ] = f.y;
        }
    }

    int lane = tid & 31, wid = tid >> 5;
#pragma unroll
    for (int co = 0; co < 16; co++) {
        float s1 = 0.f, s2 = 0.f;
        if (vt)    { s1 += ylo[co]; s2 += ylo[co]*ylo[co]; }
        if (hasHi) { s1 += yhi[co]; s2 += yhi[co]*yhi[co]; }
#pragma unroll
        for (int o = 16; o > 0; o >>= 1) {
            s1 += __shfl_down_sync(0xffffffffu, s1, o);
            s2 += __shfl_down_sync(0xffffffffu, s2, o);
        }
        if (lane == 0) {
            red[wid*16 + co]       = s1;
            red[128 + wid*16 + co] = s2;
        }
    }
    __syncthreads();
    if (tid < 16) {
        float s1 = 0.f, s2 = 0.f;
#pragma unroll
        for (int w = 0; w < 8; w++) {
            s1 += red[w*16 + tid];
            s2 += red[128 + w*16 + tid];
        }
        atomicAdd(&g_sum[tid],   (double)s1);
        atomicAdd(&g_sumsq[tid], (double)s2);
    }
}

// ---------------- BN coefficients ----------------
__global__ void coef_kernel(const float* __restrict__ gamma,
                            const float* __restrict__ beta,
                            const float* __restrict__ bias) {
    int c = threadIdx.x;
    if (c < 16) {
        double N = (double)BB * (double)D2CU;
        double mean = g_sum[c] / N;
        double var  = g_sumsq[c] / N - mean*mean;
        float a = gamma[c] * rsqrtf((float)var + 1e-5f);
        g_coef[c]      = a;
        g_coef[16 + c] = beta[c] - a * (float)mean + bias[c];
    }
}

// ---------------- BN apply + bias + relu ----------------
__global__ void apply_kernel(float* __restrict__ out) {
    int idx = blockIdx.x * 256 + threadIdx.x;   // exactly Y_ELEMS
    int c = (idx / D2CU) & 15;
    float a = g_coef[c], b = g_coef[16 + c];
    out[idx] = fmaxf(fmaf(a, g_y[idx], b), 0.f);
}

// ---------------- launch ----------------
extern "C" void kernel_launch(void* const* d_in, const int* in_sizes, int n_in,
                              void* d_out, int out_size) {
    (void)in_sizes; (void)n_in; (void)out_size;
    const float* s       = (const float*)d_in[0];
    const float* basis1  = (const float*)d_in[1];
    const float* W1      = (const float*)d_in[2];
    const float* basis2a = (const float*)d_in[3];
    const float* basis2b = (const float*)d_in[4];
    const float* W2a     = (const float*)d_in[5];
    const float* W2b     = (const float*)d_in[6];
    const float* gamma   = (const float*)d_in[7];
    const float* beta    = (const float*)d_in[8];
    const float* bias    = (const float*)d_in[9];
    float* out = (float*)d_out;

    cudaFuncSetAttribute(k1_kernel,
        cudaFuncAttributeMaxDynamicSharedMemorySize, K1_SMEM);
    cudaFuncSetAttribute(k3_kernel,
        cudaFuncAttributeMaxDynamicSharedMemorySize, K3_SMEM);

    // launch order keeps k3 in the profiler's captured (4th) slot
    setup_kernel<<<49, 256>>>(basis1, basis2a, basis2b, W1, W2a, W2b);
    k1_kernel<<<dim3(4, 4, BB*3), 256, K1_SMEM>>>(s);
    c1_kernel<<<(BB*(D1CU/2) + 255)/256, 256>>>();
    k3_kernel<<<dim3(2, 4, BB*7), 256, K3_SMEM>>>();
    c2_kernel<<<(BB*MQ + 255)/256, 256>>>();
    coef_kernel<<<1, 16>>>(gamma, beta, bias);
    apply_kernel<<<Y_ELEMS/256, 256>>>(out);
}